// round 7
// baseline (speedup 1.0000x reference)
#include <cuda_runtime.h>

__device__ __forceinline__ float fsqrt_ap(float x) {
    float r; asm("sqrt.approx.f32 %0, %1;" : "=f"(r) : "f"(x)); return r;
}
__device__ __forceinline__ float sx(float v, int m) {
    return __shfl_xor_sync(0xFFFFFFFFu, v, m, 32);
}

// Fused gate G_q = CNOT·CRX·(H⊗I) on local bits (LO=control, HI=target).
// H unnormalized (1/sqrt2^24 folded into final prob scale).
template<int LO, int HI>
__device__ __forceinline__ void step_local(float (&R)[16], float (&I)[16],
                                           float c, float s) {
    constexpr int L0 = 1 << LO, L1 = 1 << HI;
#pragma unroll
    for (int m = 0; m < 16; ++m) {
        if (m & (L0 | L1)) continue;
        const int a = m, b = m | L0, e = m | L1, d = m | L0 | L1;
        float t0;
        t0 = R[a] + R[b]; R[b] = R[a] - R[b]; R[a] = t0;
        t0 = I[a] + I[b]; I[b] = I[a] - I[b]; I[a] = t0;
        t0 = R[e] + R[d]; R[d] = R[e] - R[d]; R[e] = t0;
        t0 = I[e] + I[d]; I[d] = I[e] - I[d]; I[e] = t0;
        // CRX (s = -i*sin) then CNOT swap on (b,d)
        float xr = fmaf(s,  I[b], c * R[d]);
        float xi = fmaf(-s, R[b], c * I[d]);
        float yr = fmaf(s,  I[d], c * R[b]);
        float yi = fmaf(-s, R[d], c * I[b]);
        R[b] = xr; I[b] = xi; R[d] = yr; I[d] = yi;
    }
}

// Gate with control = local bit 3, target = lane bit (mask M).
// With CNOT: new = s*self + c*partner.  FINAL (q=11, no CNOT): new = c*self + s*partner.
template<bool FINAL>
__device__ __forceinline__ void step_shfl(float (&R)[16], float (&I)[16],
                                          float c, float s, int M) {
#pragma unroll
    for (int m = 0; m < 8; ++m) {      // H on local bit 3
        const int a = m, b = m | 8;
        float t0;
        t0 = R[a] + R[b]; R[b] = R[a] - R[b]; R[a] = t0;
        t0 = I[a] + I[b]; I[b] = I[a] - I[b]; I[a] = t0;
    }
#pragma unroll
    for (int m = 8; m < 16; ++m) {     // CRX(+CNOT) across lane bit, control==1
        float mr = R[m], mi = I[m];
        float pr = sx(mr, M), pi = sx(mi, M);
        if (FINAL) {
            R[m] = fmaf(c, mr,  s * pi);
            I[m] = fmaf(c, mi, -s * pr);
        } else {
            R[m] = fmaf(s,  mi, c * pr);
            I[m] = fmaf(-s, mr, c * pi);
        }
    }
}

// conflict-free SMEM swizzle (8-byte elements, judged per half-warp)
__device__ __forceinline__ int sw(int i) { return i ^ ((i >> 4) & 31); }

// amp-index maps: thread t (0..255), local slot j (0..15)
#define AMPA(T,J) (((T) << 4) | (J))                                   // abs 0-3 local, bit4=lane0
#define AMPB(T,J) (((T) & 15) | ((J) << 4) | (((T) >> 4) << 8))        // abs 4-7 local, bit8=lane4
#define AMPC(T,J) (((T) & 255) | ((J) << 8))                           // abs 8-11 local, bit0=lane0

__global__ void __launch_bounds__(256, 5)
quantum_kernel(const float* __restrict__ x,
               const float* __restrict__ prm,
               float* __restrict__ out) {
    __shared__ float2 buf[4096];           // 32 KB transpose buffer
    __shared__ float2 cs[12];
    __shared__ float rsum[8], rcnt[8];
    __shared__ float s_ninv, s_sc;

    const int t = threadIdx.x, lane = t & 31, w = t >> 5;
    const float* __restrict__ xr = x + (size_t)blockIdx.x * 4096;

    // load 16 consecutive floats: abs index = t*16 + j (phase-A layout)
    float v[16];
#pragma unroll
    for (int k = 0; k < 4; ++k) {
        float4 q = *reinterpret_cast<const float4*>(xr + t * 16 + k * 4);
        v[4*k] = q.x; v[4*k+1] = q.y; v[4*k+2] = q.z; v[4*k+3] = q.w;
    }
    if (t < 12) { float th = prm[t] * 0.5f; cs[t] = make_float2(cosf(th), sinf(th)); }

    // row reduction: sum of squares + nonzero count
    float ss = 0.f, cn = 0.f;
#pragma unroll
    for (int j = 0; j < 16; ++j) {
        ss = fmaf(v[j], v[j], ss);
        cn += (v[j] != 0.f) ? 1.f : 0.f;
    }
#pragma unroll
    for (int m = 16; m >= 1; m >>= 1) {
        ss += sx(ss, m);
        cn += sx(cn, m);
    }
    if (lane == 0) { rsum[w] = ss; rcnt[w] = cn; }
    __syncthreads();
    if (t == 0) {
        float S = 0.f, C = 0.f;
#pragma unroll
        for (int k = 0; k < 8; ++k) { S += rsum[k]; C += rcnt[k]; }
        s_ninv = 1.f / (sqrtf(S) + 1e-8f);
        // 1/||q||^2 * (1/sqrt2)^24 from 12 folded Hadamards
        s_sc = (C > 0.f ? 1.f / C : 0.f) * (1.f / 4096.f);
    }
    __syncthreads();
    const float ninv = s_ninv;

    // _to_quantum: re = x*ninv (|.|<1 guaranteed); im = sgn*sqrt(1-re^2), 0 if x==0
    float R[16], I[16];
#pragma unroll
    for (int j = 0; j < 16; ++j) {
        float xv = v[j];
        float r  = xv * ninv;
        float s  = fsqrt_ap(fmaxf(fmaf(-r, r, 1.f), 0.f));
        R[j] = r;
        I[j] = (xv != 0.f) ? copysignf(s, xv) : 0.f;
    }

#define LSTEP(Q,LO,HI) { float2 g = cs[Q]; step_local<LO,HI>(R, I, g.x, g.y); }
#define SSTEP(Q,M,F)   { float2 g = cs[Q]; step_shfl<F>(R, I, g.x, g.y, M); }

#define XPOSE(AW, AR) { \
    _Pragma("unroll") for (int j = 0; j < 16; ++j) \
        buf[sw(AW(t, j))] = make_float2(R[j], I[j]); \
    __syncthreads(); \
    _Pragma("unroll") for (int j = 0; j < 16; ++j) { \
        float2 a = buf[sw(AR(t, j))]; \
        R[j] = a.x; I[j] = a.y; } \
    __syncthreads(); }

    // Phase A: q=0,1,2 local on abs (0,1),(1,2),(2,3); q=3 on (3,4): lane bit0
    LSTEP(0, 0, 1) LSTEP(1, 1, 2) LSTEP(2, 2, 3)
    SSTEP(3, 1, false)
    XPOSE(AMPA, AMPB)
    // Phase B: q=4,5,6 local on abs (4,5),(5,6),(6,7); q=7 on (7,8): lane bit4
    LSTEP(4, 0, 1) LSTEP(5, 1, 2) LSTEP(6, 2, 3)
    SSTEP(7, 16, false)
    XPOSE(AMPB, AMPC)
    // Phase C: q=8,9,10 local on abs (8,9),(9,10),(10,11); q=11 on (11,0): lane bit0, NO CNOT
    LSTEP(8, 0, 1) LSTEP(9, 1, 2) LSTEP(10, 2, 3)
    SSTEP(11, 1, true)

    // output: abs = (j<<8) | t — consecutive t per j => fully coalesced 128B/warp
    const float sc = s_sc;
    float* __restrict__ orow = out + (size_t)blockIdx.x * 4096;
#pragma unroll
    for (int j = 0; j < 16; ++j) {
        orow[(j << 8) | t] = fmaf(R[j], R[j], I[j] * I[j]) * sc;
    }
}

extern "C" void kernel_launch(void* const* d_in, const int* in_sizes, int n_in,
                              void* d_out, int out_size) {
    const float* state  = (const float*)d_in[0];
    const float* params = (const float*)d_in[1];
    float* out = (float*)d_out;
    int rows = in_sizes[0] / 4096;   // 4096 rows
    quantum_kernel<<<rows, 256>>>(state, params, out);
}

// round 8
// speedup vs baseline: 1.0334x; 1.0334x over previous
#include <cuda_runtime.h>

__device__ __forceinline__ float fsqrt_ap(float x) {
    float r; asm("sqrt.approx.f32 %0, %1;" : "=f"(r) : "f"(x)); return r;
}
__device__ __forceinline__ float sx(float v, int m) {
    return __shfl_xor_sync(0xFFFFFFFFu, v, m, 32);
}

// Fused gate G_q = CNOT·CRX·(H⊗I) on local bits (LO=control, HI=target).
// H unnormalized (1/sqrt2^24 folded into final prob scale).
template<int LO, int HI>
__device__ __forceinline__ void step_local(float (&R)[16], float (&I)[16],
                                           float c, float s) {
    constexpr int L0 = 1 << LO, L1 = 1 << HI;
#pragma unroll
    for (int m = 0; m < 16; ++m) {
        if (m & (L0 | L1)) continue;
        const int a = m, b = m | L0, e = m | L1, d = m | L0 | L1;
        float t0;
        t0 = R[a] + R[b]; R[b] = R[a] - R[b]; R[a] = t0;
        t0 = I[a] + I[b]; I[b] = I[a] - I[b]; I[a] = t0;
        t0 = R[e] + R[d]; R[d] = R[e] - R[d]; R[e] = t0;
        t0 = I[e] + I[d]; I[d] = I[e] - I[d]; I[e] = t0;
        // CRX (s = -i*sin) then CNOT swap on (b,d)
        float xr = fmaf(s,  I[b], c * R[d]);
        float xi = fmaf(-s, R[b], c * I[d]);
        float yr = fmaf(s,  I[d], c * R[b]);
        float yi = fmaf(-s, R[d], c * I[b]);
        R[b] = xr; I[b] = xi; R[d] = yr; I[d] = yi;
    }
}

// Gate with control = local bit 3, target = lane bit (mask M).
// With CNOT: new = s*self + c*partner.  FINAL (q=11, no CNOT): new = c*self + s*partner.
template<bool FINAL>
__device__ __forceinline__ void step_shfl(float (&R)[16], float (&I)[16],
                                          float c, float s, int M) {
#pragma unroll
    for (int m = 0; m < 8; ++m) {      // H on local bit 3
        const int a = m, b = m | 8;
        float t0;
        t0 = R[a] + R[b]; R[b] = R[a] - R[b]; R[a] = t0;
        t0 = I[a] + I[b]; I[b] = I[a] - I[b]; I[a] = t0;
    }
#pragma unroll
    for (int m = 8; m < 16; ++m) {     // CRX(+CNOT) across lane bit, control==1
        float mr = R[m], mi = I[m];
        float pr = sx(mr, M), pi = sx(mi, M);
        if (FINAL) {
            R[m] = fmaf(c, mr,  s * pi);
            I[m] = fmaf(c, mi, -s * pr);
        } else {
            R[m] = fmaf(s,  mi, c * pr);
            I[m] = fmaf(-s, mr, c * pi);
        }
    }
}

// conflict-free SMEM swizzle (8-byte elements, judged per half-warp)
__device__ __forceinline__ int sw(int i) { return i ^ ((i >> 4) & 31); }

// amp-index maps: thread t (0..255), local slot j (0..15)
#define AMPA(T,J) (((T) << 4) | (J))                                   // abs 0-3 local, bit4=lane0
#define AMPB(T,J) (((T) & 15) | ((J) << 4) | (((T) >> 4) << 8))        // abs 4-7 local, bit8=lane4
#define AMPC(T,J) (((T) & 255) | ((J) << 8))                           // abs 8-11 local, bit0=lane0

__global__ void __launch_bounds__(256, 4)
quantum_kernel(const float* __restrict__ x,
               const float* __restrict__ prm,
               float* __restrict__ out) {
    __shared__ float2 buf[4096];           // 32 KB transpose buffer
    __shared__ float2 cs[12];
    __shared__ float2 red[8];              // per-warp (sumsq, count)

    const int t = threadIdx.x, lane = t & 31, w = t >> 5;
    const float* __restrict__ xr = x + (size_t)blockIdx.x * 4096;

    // load 16 consecutive floats: abs index = t*16 + j (phase-A layout)
    float v[16];
#pragma unroll
    for (int k = 0; k < 4; ++k) {
        float4 q = *reinterpret_cast<const float4*>(xr + t * 16 + k * 4);
        v[4*k] = q.x; v[4*k+1] = q.y; v[4*k+2] = q.z; v[4*k+3] = q.w;
    }
    if (t < 12) { float th = prm[t] * 0.5f; cs[t] = make_float2(cosf(th), sinf(th)); }

    // row reduction: sum of squares + nonzero count
    float ss = 0.f, cn = 0.f;
#pragma unroll
    for (int j = 0; j < 16; ++j) {
        ss = fmaf(v[j], v[j], ss);
        cn += (v[j] != 0.f) ? 1.f : 0.f;
    }
#pragma unroll
    for (int m = 16; m >= 1; m >>= 1) {
        ss += sx(ss, m);
        cn += sx(cn, m);
    }
    if (lane == 0) { red[w] = make_float2(ss, cn); }
    __syncthreads();
    // every thread folds the 8 partials itself (saves a barrier + t0 serialization)
    float S = 0.f, C = 0.f;
#pragma unroll
    for (int k = 0; k < 8; ++k) { float2 p = red[k]; S += p.x; C += p.y; }
    const float ninv = 1.f / (sqrtf(S) + 1e-8f);
    // 1/||q||^2 * (1/sqrt2)^24 from 12 folded Hadamards
    const float sc = (C > 0.f ? 1.f / C : 0.f) * (1.f / 4096.f);

    // _to_quantum: re = x*ninv (|.| < 1 guaranteed); im = sgn*sqrt(1-re^2), 0 if x==0
    float R[16], I[16];
#pragma unroll
    for (int j = 0; j < 16; ++j) {
        float xv = v[j];
        float r  = xv * ninv;
        float s  = fsqrt_ap(fmaxf(fmaf(-r, r, 1.f), 0.f));
        R[j] = r;
        I[j] = (xv != 0.f) ? copysignf(s, xv) : 0.f;
    }

#define LSTEP(Q,LO,HI) { float2 g = cs[Q]; step_local<LO,HI>(R, I, g.x, g.y); }
#define SSTEP(Q,M,F)   { float2 g = cs[Q]; step_shfl<F>(R, I, g.x, g.y, M); }

#define XPOSE(AW, AR) { \
    _Pragma("unroll") for (int j = 0; j < 16; ++j) \
        buf[sw(AW(t, j))] = make_float2(R[j], I[j]); \
    __syncthreads(); \
    _Pragma("unroll") for (int j = 0; j < 16; ++j) { \
        float2 a = buf[sw(AR(t, j))]; \
        R[j] = a.x; I[j] = a.y; } \
    __syncthreads(); }

    // Phase A: q=0,1,2 local on abs (0,1),(1,2),(2,3); q=3 on (3,4): lane bit0
    LSTEP(0, 0, 1) LSTEP(1, 1, 2) LSTEP(2, 2, 3)
    SSTEP(3, 1, false)
    XPOSE(AMPA, AMPB)
    // Phase B: q=4,5,6 local on abs (4,5),(5,6),(6,7); q=7 on (7,8): lane bit4
    LSTEP(4, 0, 1) LSTEP(5, 1, 2) LSTEP(6, 2, 3)
    SSTEP(7, 16, false)
    XPOSE(AMPB, AMPC)
    // Phase C: q=8,9,10 local on abs (8,9),(9,10),(10,11); q=11 on (11,0): lane bit0, NO CNOT
    LSTEP(8, 0, 1) LSTEP(9, 1, 2) LSTEP(10, 2, 3)
    SSTEP(11, 1, true)

    // output: abs = (j<<8) | t — consecutive t per j => fully coalesced 128B/warp
    float* __restrict__ orow = out + (size_t)blockIdx.x * 4096;
#pragma unroll
    for (int j = 0; j < 16; ++j) {
        orow[(j << 8) | t] = fmaf(R[j], R[j], I[j] * I[j]) * sc;
    }
}

extern "C" void kernel_launch(void* const* d_in, const int* in_sizes, int n_in,
                              void* d_out, int out_size) {
    const float* state  = (const float*)d_in[0];
    const float* params = (const float*)d_in[1];
    float* out = (float*)d_out;
    int rows = in_sizes[0] / 4096;   // 4096 rows
    quantum_kernel<<<rows, 256>>>(state, params, out);
}